// round 1
// baseline (speedup 1.0000x reference)
#include <cuda_runtime.h>
#include <cuda_bf16.h>

// Problem constants (fixed shapes from reference)
#define BB 8
#define NN 4096
#define EE 64
#define KK 32

#define DELTA_V 0.5f
#define DELTA_D 1.5f
#define GAMMA   0.001f

// Scratch (no cudaMalloc allowed) ------------------------------------------
__device__ float g_csum[BB * KK * EE];   // centroid sums, then normalized centroids
__device__ float g_cnt[BB * KK];         // points per cluster
__device__ int   g_lab[BB * NN];         // per-point cluster label
__device__ float g_acc[4];               // [0]=L_v sum, [1]=L_d sum, [2]=L_r sum

// --------------------------------------------------------------------------
__global__ void k_zero() {
    int i = blockIdx.x * blockDim.x + threadIdx.x;
    if (i < BB * KK * EE) g_csum[i] = 0.0f;
    if (i < BB * KK)      g_cnt[i]  = 0.0f;
    if (i < 4)            g_acc[i]  = 0.0f;
}

// Warp-per-point centroid accumulation. 128 points/block, 8 warps x 16 iters.
__global__ void __launch_bounds__(256) k_centroid(const float* __restrict__ x,
                                                  const float* __restrict__ m) {
    __shared__ float sc[KK * EE];
    __shared__ float scnt[KK];
    int tid = threadIdx.x, lane = tid & 31, warp = tid >> 5;

    for (int i = tid; i < KK * EE; i += 256) sc[i] = 0.0f;
    if (tid < KK) scnt[tid] = 0.0f;
    __syncthreads();

    int pbase = blockIdx.x * 128;          // N divisible by 128 -> block within one batch
    #pragma unroll 1
    for (int it = 0; it < 16; ++it) {
        int p = pbase + it * 8 + warp;
        float mv = m[(size_t)p * KK + lane];           // one-hot row
        unsigned bal = __ballot_sync(0xffffffffu, mv > 0.5f);
        int label = __ffs(bal) - 1;
        const float* xp = x + (size_t)p * EE;
        float x0 = xp[lane], x1 = xp[lane + 32];
        atomicAdd(&sc[label * EE + lane], x0);
        atomicAdd(&sc[label * EE + lane + 32], x1);
        if (lane == 0) {
            atomicAdd(&scnt[label], 1.0f);
            g_lab[p] = label;
        }
    }
    __syncthreads();

    int b = pbase / NN;
    for (int i = tid; i < KK * EE; i += 256)
        atomicAdd(&g_csum[b * KK * EE + i], sc[i]);
    if (tid < KK) atomicAdd(&g_cnt[b * KK + tid], scnt[tid]);
}

// One block per batch: normalize centroids, compute L_d (pairwise hinge) + L_r.
__global__ void __launch_bounds__(256) k_pairs() {
    __shared__ float c[KK * EE];
    int b = blockIdx.x, tid = threadIdx.x;

    for (int i = tid; i < KK * EE; i += 256) {
        int k = i / EE;
        float v = g_csum[b * KK * EE + i] / g_cnt[b * KK + k];
        c[i] = v;
        g_csum[b * KK * EE + i] = v;   // write normalized centroid back for k_var
    }
    __syncthreads();

    float ld = 0.0f, lr = 0.0f;
    for (int pr = tid; pr < KK * KK; pr += 256) {
        int k1 = pr >> 5, k2 = pr & 31;
        float sq = 0.0f;
        if (k1 == k2) {
            #pragma unroll
            for (int e = 0; e < EE; e++) { float v = c[k1 * EE + e]; sq += v * v; }
            lr += sqrtf(sq);                         // safe: sqrt(0)=0
        } else {
            #pragma unroll
            for (int e = 0; e < EE; e++) {
                float d = c[k1 * EE + e] - c[k2 * EE + e];
                sq += d * d;
            }
            float h = 2.0f * DELTA_D - sqrtf(sq);
            if (h > 0.0f) ld += h * h;
        }
    }
    #pragma unroll
    for (int o = 16; o; o >>= 1) {
        ld += __shfl_xor_sync(0xffffffffu, ld, o);
        lr += __shfl_xor_sync(0xffffffffu, lr, o);
    }
    if ((tid & 31) == 0) {
        atomicAdd(&g_acc[1], ld);
        atomicAdd(&g_acc[2], lr);
    }
}

// Warp-per-point variance hinge. Centroids live in L2 by now.
__global__ void __launch_bounds__(256) k_var(const float* __restrict__ x) {
    int tid = threadIdx.x, lane = tid & 31, warp = tid >> 5;
    int pbase = blockIdx.x * 128;
    int b = pbase / NN;
    float lv = 0.0f;

    #pragma unroll 1
    for (int it = 0; it < 16; ++it) {
        int p = pbase + it * 8 + warp;
        int label = g_lab[p];
        const float* xp = x + (size_t)p * EE;
        const float* cp = g_csum + ((size_t)b * KK + label) * EE;
        float d0 = xp[lane] - cp[lane];
        float d1 = xp[lane + 32] - cp[lane + 32];
        float sq = d0 * d0 + d1 * d1;
        #pragma unroll
        for (int o = 16; o; o >>= 1) sq += __shfl_xor_sync(0xffffffffu, sq, o);
        float h = sqrtf(sq) - DELTA_V;
        if (h > 0.0f) lv += h * h;
    }
    if (lane == 0) atomicAdd(&g_acc[0], lv);
}

__global__ void k_final(float* __restrict__ out) {
    float Lv = g_acc[0] / (float)(BB * NN);
    float Ld = g_acc[1] / (float)(BB * KK * (KK - 1));
    float Lr = g_acc[2] / (float)(BB * KK);
    out[0] = Lv + Ld + GAMMA * Lr;
}

// --------------------------------------------------------------------------
extern "C" void kernel_launch(void* const* d_in, const int* in_sizes, int n_in,
                              void* d_out, int out_size) {
    // Identify inputs by size (embedded = B*N*E, masks = B*N*K)
    const float* x = (const float*)d_in[0];
    const float* m = (const float*)d_in[1];
    if (in_sizes[0] == BB * NN * KK && in_sizes[1] == BB * NN * EE) {
        x = (const float*)d_in[1];
        m = (const float*)d_in[0];
    }

    k_zero<<<(BB * KK * EE + 255) / 256, 256>>>();
    k_centroid<<<BB * NN / 128, 256>>>(x, m);
    k_pairs<<<BB, 256>>>();
    k_var<<<BB * NN / 128, 256>>>(x);
    k_final<<<1, 1>>>((float*)d_out);
}

// round 2
// speedup vs baseline: 1.1852x; 1.1852x over previous
#include <cuda_runtime.h>
#include <cuda_bf16.h>

// Fixed problem shape
#define BB 8
#define NN 4096
#define EE 64
#define KK 32

#define DELTA_V 0.5f
#define DELTA_D 1.5f
#define GAMMA   0.001f

#define CGRID 128    // centroid blocks (256 points each)
#define VGRID 1024   // variance blocks (32 points each)

// Scratch ------------------------------------------------------------------
__device__ float    g_csum[BB * KK * EE];   // RAW centroid sums (never normalized in place)
__device__ float    g_cnt[BB * KK];         // points per cluster
__device__ int      g_lab[BB * NN];         // per-point label
__device__ float    g_acc[3];               // [0]=L_v, [1]=L_d, [2]=L_r (unnormalized sums)
__device__ unsigned g_ctr;                  // last-block counter for k_pairs

// --------------------------------------------------------------------------
__global__ void k_zero() {
    int i = blockIdx.x * blockDim.x + threadIdx.x;   // 64*256 = 16384 threads
    g_csum[i] = 0.0f;
    if (i < BB * KK) g_cnt[i] = 0.0f;
    if (i < 3)       g_acc[i] = 0.0f;
    if (i == 0)      g_ctr    = 0u;
}

// Labels + centroid sums. 8 warps, 2 points per warp per iter, 16 iters = 256 pts/block.
__global__ void __launch_bounds__(256) k_centroid(const float* __restrict__ x,
                                                  const float* __restrict__ m) {
    __shared__ float sc[KK * EE];
    __shared__ float scnt[KK];
    int tid = threadIdx.x, lane = tid & 31, warp = tid >> 5;

    for (int i = tid; i < KK * EE; i += 256) sc[i] = 0.0f;
    if (tid < KK) scnt[tid] = 0.0f;
    __syncthreads();

    int pbase = blockIdx.x * 256;           // 4096/256=16 blocks per batch -> single batch
    int b = pbase / NN;

    #pragma unroll 1
    for (int it = 0; it < 16; ++it) {
        int p0 = pbase + it * 16 + warp * 2;
        int p1 = p0 + 1;
        float mv0 = m[(size_t)p0 * KK + lane];
        float mv1 = m[(size_t)p1 * KK + lane];
        unsigned b0 = __ballot_sync(0xffffffffu, mv0 > 0.5f);
        unsigned b1 = __ballot_sync(0xffffffffu, mv1 > 0.5f);
        int lab0 = __ffs(b0) - 1;
        int lab1 = __ffs(b1) - 1;
        float2 xv0 = *(const float2*)(x + (size_t)p0 * EE + lane * 2);
        float2 xv1 = *(const float2*)(x + (size_t)p1 * EE + lane * 2);
        atomicAdd(&sc[lab0 * EE + lane * 2],     xv0.x);
        atomicAdd(&sc[lab0 * EE + lane * 2 + 1], xv0.y);
        atomicAdd(&sc[lab1 * EE + lane * 2],     xv1.x);
        atomicAdd(&sc[lab1 * EE + lane * 2 + 1], xv1.y);
        if (lane == 0) {
            atomicAdd(&scnt[lab0], 1.0f);
            atomicAdd(&scnt[lab1], 1.0f);
            g_lab[p0] = lab0;
            g_lab[p1] = lab1;
        }
    }
    __syncthreads();

    for (int i = tid; i < KK * EE; i += 256)
        atomicAdd(&g_csum[b * KK * EE + i], sc[i]);
    if (tid < KK) atomicAdd(&g_cnt[b * KK + tid], scnt[tid]);
}

// Variance hinge. 16-lane group per point, float4 loads, raw sums * 1/count.
__global__ void __launch_bounds__(256) k_var(const float* __restrict__ x) {
    int tid = threadIdx.x, gid = tid >> 4, gl = tid & 15;
    int pbase = blockIdx.x * 32;            // 4096/32=128 blocks per batch -> single batch
    int b = pbase >> 12;                    // / NN
    float lv = 0.0f;

    #pragma unroll
    for (int it = 0; it < 2; ++it) {
        int p = pbase + it * 16 + gid;
        int lab = g_lab[p];
        float inv = 1.0f / g_cnt[b * KK + lab];
        float4 xv = *(const float4*)(x + (size_t)p * EE + gl * 4);
        float4 cs = *(const float4*)(g_csum + ((size_t)b * KK + lab) * EE + gl * 4);
        float d0 = xv.x - cs.x * inv;
        float d1 = xv.y - cs.y * inv;
        float d2 = xv.z - cs.z * inv;
        float d3 = xv.w - cs.w * inv;
        float sq = d0 * d0 + d1 * d1 + d2 * d2 + d3 * d3;
        #pragma unroll
        for (int o = 8; o; o >>= 1) sq += __shfl_xor_sync(0xffffffffu, sq, o);
        if (gl == 0) {
            float h = sqrtf(sq) - DELTA_V;
            if (h > 0.0f) lv += h * h;
        }
    }

    __shared__ float bsum;
    if (tid == 0) bsum = 0.0f;
    __syncthreads();
    if (gl == 0) atomicAdd(&bsum, lv);
    __syncthreads();
    if (tid == 0) atomicAdd(&g_acc[0], bsum);
}

// Pairwise centroid hinge + reg term; last block folds in the final scalar.
__global__ void __launch_bounds__(256) k_pairs(float* __restrict__ out) {
    __shared__ float c[KK * EE];
    int b = blockIdx.x, tid = threadIdx.x;

    for (int i = tid; i < KK * EE; i += 256) {
        int k = i / EE;
        c[i] = g_csum[b * KK * EE + i] / g_cnt[b * KK + k];
    }
    __syncthreads();

    float ld = 0.0f, lr = 0.0f;
    for (int pr = tid; pr < KK * KK; pr += 256) {
        int k1 = pr >> 5, k2 = pr & 31;
        float sq = 0.0f;
        if (k1 == k2) {
            #pragma unroll
            for (int e = 0; e < EE; e++) { float v = c[k1 * EE + e]; sq += v * v; }
            lr += sqrtf(sq);
        } else {
            #pragma unroll
            for (int e = 0; e < EE; e++) {
                float d = c[k1 * EE + e] - c[k2 * EE + e];
                sq += d * d;
            }
            float h = 2.0f * DELTA_D - sqrtf(sq);
            if (h > 0.0f) ld += h * h;
        }
    }
    #pragma unroll
    for (int o = 16; o; o >>= 1) {
        ld += __shfl_xor_sync(0xffffffffu, ld, o);
        lr += __shfl_xor_sync(0xffffffffu, lr, o);
    }
    if ((tid & 31) == 0) {
        atomicAdd(&g_acc[1], ld);
        atomicAdd(&g_acc[2], lr);
    }

    // Last-block finalization
    __threadfence();
    __syncthreads();
    __shared__ unsigned done;
    if (tid == 0) done = atomicAdd(&g_ctr, 1u);
    __syncthreads();
    if (done == gridDim.x - 1 && tid == 0) {
        float Lv = atomicAdd(&g_acc[0], 0.0f) / (float)(BB * NN);
        float Ld = atomicAdd(&g_acc[1], 0.0f) / (float)(BB * KK * (KK - 1));
        float Lr = atomicAdd(&g_acc[2], 0.0f) / (float)(BB * KK);
        out[0] = Lv + Ld + GAMMA * Lr;
    }
}

// --------------------------------------------------------------------------
extern "C" void kernel_launch(void* const* d_in, const int* in_sizes, int n_in,
                              void* d_out, int out_size) {
    const float* x = (const float*)d_in[0];
    const float* m = (const float*)d_in[1];
    if (in_sizes[0] == BB * NN * KK && in_sizes[1] == BB * NN * EE) {
        x = (const float*)d_in[1];
        m = (const float*)d_in[0];
    }

    k_zero<<<BB * KK * EE / 256, 256>>>();
    k_centroid<<<CGRID, 256>>>(x, m);
    k_var<<<VGRID, 256>>>(x);
    k_pairs<<<BB, 256>>>((float*)d_out);
}

// round 3
// speedup vs baseline: 1.2601x; 1.0632x over previous
#include <cuda_runtime.h>
#include <cuda_bf16.h>

// Fixed problem shape
#define BB 8
#define NN 4096
#define EE 64
#define KK 32

#define DELTA_V 0.5f
#define DELTA_D 1.5f
#define GAMMA   0.001f

#define GRID 128          // <= SM count (148) -> all blocks co-resident, spin barriers safe
#define PTS  256          // points per block (128*256 = 32768 = B*N)
#define SMEM_DYN (PTS * EE * 4)   // 64KB: block's x points (aliased as ct in pairs phase)

// Scratch ------------------------------------------------------------------
__device__ float    g_csum[BB * KK * EE];   // raw centroid sums
__device__ float    g_cnt[BB * KK];         // points per cluster
__device__ float    g_acc[3];               // L_v, L_d, L_r (unnormalized)
__device__ unsigned g_bar = 0;              // grid barrier counter (reset by finalizer)

__device__ __forceinline__ void grid_barrier(unsigned target) {
    __syncthreads();
    if (threadIdx.x == 0) {
        __threadfence();
        atomicAdd(&g_bar, 1u);
        while (atomicAdd(&g_bar, 0u) < target) { }
    }
    __syncthreads();
}

__global__ void __launch_bounds__(256) fused(const float* __restrict__ x,
                                             const float* __restrict__ m,
                                             float* __restrict__ out) {
    extern __shared__ float sx[];           // [PTS*EE] x points; reused as ct[E][K] in pairs
    __shared__ float sc[KK * EE];           // partial sums, then normalized centroids
    __shared__ float scnt[KK];
    __shared__ float sinv[KK];
    __shared__ int   slab[PTS];
    __shared__ float bsum;

    int tid = threadIdx.x, lane = tid & 31, warp = tid >> 5;
    int pbase = blockIdx.x * PTS;
    int b = blockIdx.x >> 4;                // 16 blocks per batch

    // ---- Phase 0: zero global scratch -------------------------------------
    if (tid < 128) g_csum[blockIdx.x * 128 + tid] = 0.0f;   // 128*128 = 16384
    if (blockIdx.x == 0) {
        g_cnt[tid] = 0.0f;                                  // 256 entries
        if (tid < 3) g_acc[tid] = 0.0f;
    }
    for (int i = tid; i < KK * EE; i += 256) sc[i] = 0.0f;
    if (tid < KK) scnt[tid] = 0.0f;
    if (tid == 0) bsum = 0.0f;
    grid_barrier(GRID);                     // zeros visible everywhere

    // ---- Phase 1: labels + centroid partial sums; stash x in smem ---------
    #pragma unroll 1
    for (int it = 0; it < 16; ++it) {
        int l0 = it * 16 + warp * 2;        // local point indices
        int l1 = l0 + 1;
        int p0 = pbase + l0, p1 = pbase + l1;
        float mv0 = m[(size_t)p0 * KK + lane];
        float mv1 = m[(size_t)p1 * KK + lane];
        unsigned b0 = __ballot_sync(0xffffffffu, mv0 > 0.5f);
        unsigned b1 = __ballot_sync(0xffffffffu, mv1 > 0.5f);
        int lab0 = __ffs(b0) - 1;
        int lab1 = __ffs(b1) - 1;
        float2 xv0 = *(const float2*)(x + (size_t)p0 * EE + lane * 2);
        float2 xv1 = *(const float2*)(x + (size_t)p1 * EE + lane * 2);
        ((float2*)sx)[l0 * 32 + lane] = xv0;
        ((float2*)sx)[l1 * 32 + lane] = xv1;
        atomicAdd(&sc[lab0 * EE + lane * 2],     xv0.x);
        atomicAdd(&sc[lab0 * EE + lane * 2 + 1], xv0.y);
        atomicAdd(&sc[lab1 * EE + lane * 2],     xv1.x);
        atomicAdd(&sc[lab1 * EE + lane * 2 + 1], xv1.y);
        if (lane == 0) {
            atomicAdd(&scnt[lab0], 1.0f);
            atomicAdd(&scnt[lab1], 1.0f);
            slab[l0] = lab0;
            slab[l1] = lab1;
        }
    }
    __syncthreads();
    for (int i = tid; i < KK * EE; i += 256)
        atomicAdd(&g_csum[b * KK * EE + i], sc[i]);
    if (tid < KK) atomicAdd(&g_cnt[b * KK + tid], scnt[tid]);
    grid_barrier(2 * GRID);                 // centroid sums final

    // ---- Phase 2: normalized centroids -> smem, variance hinge ------------
    if (tid < KK) sinv[tid] = 1.0f / __ldcg(&g_cnt[b * KK + tid]);
    __syncthreads();
    for (int i = tid; i < KK * EE; i += 256)
        sc[i] = __ldcg(&g_csum[b * KK * EE + i]) * sinv[i >> 6];
    __syncthreads();

    {
        int gid = tid >> 4, gl = tid & 15;  // 16-lane group per point
        float lv = 0.0f;
        #pragma unroll 4
        for (int it = 0; it < 16; ++it) {
            int idx = it * 16 + gid;
            int lab = slab[idx];
            float4 xv = ((const float4*)sx)[idx * 16 + gl];
            float4 cv = ((const float4*)sc)[lab * 16 + gl];
            float d0 = xv.x - cv.x, d1 = xv.y - cv.y;
            float d2 = xv.z - cv.z, d3 = xv.w - cv.w;
            float sq = d0 * d0 + d1 * d1 + d2 * d2 + d3 * d3;
            #pragma unroll
            for (int o = 8; o; o >>= 1) sq += __shfl_xor_sync(0xffffffffu, sq, o);
            if (gl == 0) {
                float h = sqrtf(sq) - DELTA_V;
                if (h > 0.0f) lv += h * h;
            }
        }
        if (gl == 0) atomicAdd(&bsum, lv);
        __syncthreads();
        if (tid == 0) atomicAdd(&g_acc[0], bsum);
    }

    // ---- Phase 3: pairwise hinge + reg (one block per batch) --------------
    if ((blockIdx.x & 15) == 0) {
        __syncthreads();                    // sx no longer needed -> reuse as ct
        float* ct = sx;                     // ct[e*KK + k] transposed centroids
        for (int i = tid; i < KK * EE; i += 256) {
            int e = i >> 5, k = i & 31;
            ct[i] = sc[k * EE + e];
        }
        __syncthreads();

        float ld = 0.0f, lr = 0.0f;
        for (int pr = tid; pr < KK * KK; pr += 256) {
            int k1 = pr >> 5, k2 = pr & 31; // k1 constant per warp, k2 = lane
            float sq = 0.0f;
            if (k1 == k2) {
                #pragma unroll
                for (int e = 0; e < EE; e++) { float v = sc[k1 * EE + e]; sq += v * v; }
                lr += sqrtf(sq);
            } else {
                #pragma unroll
                for (int e = 0; e < EE; e++) {
                    float d = sc[k1 * EE + e] - ct[e * KK + k2];  // broadcast - contiguous
                    sq += d * d;
                }
                float h = 2.0f * DELTA_D - sqrtf(sq);
                if (h > 0.0f) ld += h * h;
            }
        }
        #pragma unroll
        for (int o = 16; o; o >>= 1) {
            ld += __shfl_xor_sync(0xffffffffu, ld, o);
            lr += __shfl_xor_sync(0xffffffffu, lr, o);
        }
        if (lane == 0) {
            atomicAdd(&g_acc[1], ld);
            atomicAdd(&g_acc[2], lr);
        }
    }

    // ---- Finalize: last arrival writes output + resets barrier ------------
    __syncthreads();
    if (tid == 0) {
        __threadfence();
        unsigned r = atomicAdd(&g_bar, 1u);
        if (r == 3 * GRID - 1) {
            float Lv = atomicAdd(&g_acc[0], 0.0f) / (float)(BB * NN);
            float Ld = atomicAdd(&g_acc[1], 0.0f) / (float)(BB * KK * (KK - 1));
            float Lr = atomicAdd(&g_acc[2], 0.0f) / (float)(BB * KK);
            out[0] = Lv + Ld + GAMMA * Lr;
            __threadfence();
            atomicExch(&g_bar, 0u);         // ready for next graph replay
        }
    }
}

// --------------------------------------------------------------------------
extern "C" void kernel_launch(void* const* d_in, const int* in_sizes, int n_in,
                              void* d_out, int out_size) {
    const float* x = (const float*)d_in[0];
    const float* m = (const float*)d_in[1];
    if (in_sizes[0] == BB * NN * KK && in_sizes[1] == BB * NN * EE) {
        x = (const float*)d_in[1];
        m = (const float*)d_in[0];
    }
    cudaFuncSetAttribute(fused, cudaFuncAttributeMaxDynamicSharedMemorySize, SMEM_DYN);
    fused<<<GRID, 256, SMEM_DYN>>>(x, m, (float*)d_out);
}

// round 5
// speedup vs baseline: 1.8941x; 1.5031x over previous
#include <cuda_runtime.h>
#include <cuda_bf16.h>

// Fixed problem shape
#define BB 8
#define NN 4096
#define EE 64
#define KK 32

#define DELTA_V 0.5f
#define DELTA_D 1.5f
#define GAMMA   0.001f

#define GRID 128          // <= SM count -> all co-resident, spin barrier safe
#define TPB  512
#define PTS  256          // points per block

// Scratch ------------------------------------------------------------------
__device__ float    g_part[GRID * KK * EE];  // per-block centroid partial sums
__device__ float    g_pcnt[GRID * KK];       // per-block cluster counts
__device__ float    g_acc[3];                // L_v, L_d, L_r (unnormalized)
__device__ unsigned g_bar = 0;               // barrier/final counter (reset each run)

__device__ __forceinline__ void grid_barrier(unsigned target) {
    __syncthreads();
    if (threadIdx.x == 0) {
        __threadfence();
        atomicAdd(&g_bar, 1u);
        while (atomicAdd(&g_bar, 0u) < target) { __nanosleep(64); }
    }
    __syncthreads();
}

__global__ void __launch_bounds__(TPB) fused(const float* __restrict__ x,
                                             const float* __restrict__ m,
                                             float* __restrict__ out) {
    __shared__ float sc[KK * EE];     // normalized centroids (phase 2+)
    __shared__ float ct[KK * EE];     // transposed centroids (phase 3)
    __shared__ int   slab[PTS];       // per-local-point label
    __shared__ int   ssorted[PTS];    // point indices sorted by label
    __shared__ int   sbin[KK], soff[KK], scur[KK];
    __shared__ float sinv[KK];
    __shared__ float bsum;

    int tid = threadIdx.x, lane = tid & 31, warp = tid >> 5;
    int blk = blockIdx.x;
    int pbase = blk * PTS;
    int b = blk >> 4;                 // 16 blocks per batch

    if (tid == 0) bsum = 0.0f;
    if (tid < KK) sbin[tid] = 0;
    if (blk == 0 && tid < 3) g_acc[tid] = 0.0f;
    __syncthreads();

    // ---- Phase 1a: labels via ballot ------------------------------------
    #pragma unroll 1
    for (int it = 0; it < 8; ++it) {
        int p0 = it * 32 + warp * 2;
        int p1 = p0 + 1;
        float mv0 = m[(size_t)(pbase + p0) * KK + lane];
        float mv1 = m[(size_t)(pbase + p1) * KK + lane];
        int lab0 = __ffs(__ballot_sync(0xffffffffu, mv0 > 0.5f)) - 1;
        int lab1 = __ffs(__ballot_sync(0xffffffffu, mv1 > 0.5f)) - 1;
        if (lane == 0) { slab[p0] = lab0; slab[p1] = lab1; }
    }
    __syncthreads();

    // ---- Phase 1b: counting sort of point indices by label ---------------
    if (tid < PTS) atomicAdd(&sbin[slab[tid]], 1);
    __syncthreads();
    if (tid < KK) {                   // warp 0: exclusive scan over 32 bins
        int c = sbin[tid];
        int pref = c;
        #pragma unroll
        for (int o = 1; o < 32; o <<= 1) {
            int nv = __shfl_up_sync(0xffffffffu, pref, o);
            if (lane >= o) pref += nv;
        }
        soff[tid] = pref - c;
        scur[tid] = pref - c;
    }
    __syncthreads();
    if (tid < PTS) {
        int lab = slab[tid];
        int pos = atomicAdd(&scur[lab], 1);
        ssorted[pos] = tid;
    }
    __syncthreads();

    // ---- Phase 1c: register-accumulated centroid partials (no atomics) ----
    #pragma unroll
    for (int kb = 0; kb < 2; ++kb) {
        int k = warp * 2 + kb;
        int start = soff[k], cnt = sbin[k], end = start + cnt;
        float ax = 0.0f, ay = 0.0f;
        for (int base = start; base < end; base += 4) {
            float2 v0 = {0,0}, v1 = {0,0}, v2 = {0,0}, v3 = {0,0};
            v0 = *(const float2*)(x + (size_t)(pbase + ssorted[base]) * EE + lane * 2);
            if (base + 1 < end) v1 = *(const float2*)(x + (size_t)(pbase + ssorted[base+1]) * EE + lane * 2);
            if (base + 2 < end) v2 = *(const float2*)(x + (size_t)(pbase + ssorted[base+2]) * EE + lane * 2);
            if (base + 3 < end) v3 = *(const float2*)(x + (size_t)(pbase + ssorted[base+3]) * EE + lane * 2);
            ax += (v0.x + v1.x) + (v2.x + v3.x);
            ay += (v0.y + v1.y) + (v2.y + v3.y);
        }
        float2 acc = {ax, ay};
        *(float2*)(&g_part[(size_t)blk * (KK*EE) + k * EE + lane * 2]) = acc;
        if (lane == 0) g_pcnt[blk * KK + k] = (float)cnt;
    }

    grid_barrier(GRID);               // all partials + g_acc zeros visible

    // ---- Phase 2a: reduce partials -> normalized centroids in smem --------
    if (tid < KK) {
        float c = 0.0f;
        #pragma unroll
        for (int j = 0; j < 16; ++j)
            c += __ldcg(&g_pcnt[((b << 4) + j) * KK + tid]);
        sinv[tid] = 1.0f / c;
    }
    __syncthreads();
    for (int i = tid; i < KK * EE; i += TPB) {
        float s = 0.0f;
        #pragma unroll
        for (int j = 0; j < 16; ++j)
            s += __ldcg(&g_part[(size_t)((b << 4) + j) * (KK*EE) + i]);
        sc[i] = s * sinv[i >> 6];
    }
    __syncthreads();

    // ---- Phase 2b: variance hinge (x re-read from warm L2), 2-pt ILP ------
    {
        int gid = tid >> 4, gl = tid & 15;    // 16-lane group per point
        float lv = 0.0f;
        #pragma unroll
        for (int it = 0; it < 4; ++it) {
            int iA = it * 64 + gid;
            int iB = iA + 32;
            int labA = slab[iA], labB = slab[iB];
            float4 xA = *(const float4*)(x + (size_t)(pbase + iA) * EE + gl * 4);
            float4 xB = *(const float4*)(x + (size_t)(pbase + iB) * EE + gl * 4);
            float4 cA = ((const float4*)sc)[labA * 16 + gl];
            float4 cB = ((const float4*)sc)[labB * 16 + gl];
            float a0 = xA.x - cA.x, a1 = xA.y - cA.y, a2 = xA.z - cA.z, a3 = xA.w - cA.w;
            float b0 = xB.x - cB.x, b1 = xB.y - cB.y, b2 = xB.z - cB.z, b3 = xB.w - cB.w;
            float sqA = a0 * a0 + a1 * a1 + a2 * a2 + a3 * a3;
            float sqB = b0 * b0 + b1 * b1 + b2 * b2 + b3 * b3;
            #pragma unroll
            for (int o = 8; o; o >>= 1) {
                sqA += __shfl_xor_sync(0xffffffffu, sqA, o);
                sqB += __shfl_xor_sync(0xffffffffu, sqB, o);
            }
            if (gl == 0) {
                float hA = sqrtf(sqA) - DELTA_V;
                float hB = sqrtf(sqB) - DELTA_V;
                if (hA > 0.0f) lv += hA * hA;
                if (hB > 0.0f) lv += hB * hB;
            }
        }
        if (gl == 0) atomicAdd(&bsum, lv);
        __syncthreads();
        if (tid == 0) atomicAdd(&g_acc[0], bsum);
    }

    // ---- Phase 3: pairwise hinge + reg term (one block per batch) ---------
    if ((blk & 15) == 0) {
        for (int i = tid; i < KK * EE; i += TPB) {
            int e = i >> 5, k = i & 31;
            ct[i] = sc[k * EE + e];           // ct[e][k], lane-contiguous
        }
        __syncthreads();

        float ld = 0.0f, lr = 0.0f;
        #pragma unroll
        for (int rep = 0; rep < 2; ++rep) {
            int pr = rep * TPB + tid;
            int k1 = pr >> 5, k2 = pr & 31;
            float sq = 0.0f;
            if (k1 == k2) {
                #pragma unroll
                for (int e = 0; e < EE; e++) { float v = sc[k1 * EE + e]; sq += v * v; }
                lr += sqrtf(sq);
            } else {
                #pragma unroll
                for (int e = 0; e < EE; e++) {
                    float d = sc[k1 * EE + e] - ct[e * KK + k2];
                    sq += d * d;
                }
                float h = 2.0f * DELTA_D - sqrtf(sq);
                if (h > 0.0f) ld += h * h;
            }
        }
        #pragma unroll
        for (int o = 16; o; o >>= 1) {
            ld += __shfl_xor_sync(0xffffffffu, ld, o);
            lr += __shfl_xor_sync(0xffffffffu, lr, o);
        }
        if (lane == 0) {
            atomicAdd(&g_acc[1], ld);
            atomicAdd(&g_acc[2], lr);
        }
    }

    // ---- Finalize: last arrival writes out + resets barrier ---------------
    __syncthreads();
    if (tid == 0) {
        __threadfence();
        unsigned r = atomicAdd(&g_bar, 1u);
        if (r == 2 * GRID - 1) {
            float Lv = atomicAdd(&g_acc[0], 0.0f) / (float)(BB * NN);
            float Ld = atomicAdd(&g_acc[1], 0.0f) / (float)(BB * KK * (KK - 1));
            float Lr = atomicAdd(&g_acc[2], 0.0f) / (float)(BB * KK);
            out[0] = Lv + Ld + GAMMA * Lr;
            __threadfence();
            atomicExch(&g_bar, 0u);       // ready for next graph replay
        }
    }
}

// --------------------------------------------------------------------------
extern "C" void kernel_launch(void* const* d_in, const int* in_sizes, int n_in,
                              void* d_out, int out_size) {
    const float* x = (const float*)d_in[0];
    const float* m = (const float*)d_in[1];
    if (in_sizes[0] == BB * NN * KK && in_sizes[1] == BB * NN * EE) {
        x = (const float*)d_in[1];
        m = (const float*)d_in[0];
    }
    fused<<<GRID, TPB>>>(x, m, (float*)d_out);
}

// round 6
// speedup vs baseline: 1.9271x; 1.0174x over previous
#include <cuda_runtime.h>
#include <cuda_bf16.h>

// Fixed problem shape
#define BB 8
#define NN 4096
#define EE 64
#define KK 32

#define DELTA_V 0.5f
#define DELTA_D 1.5f
#define GAMMA   0.001f

#define GRID 256          // 2 blocks/SM, all co-resident (occ limit 4) -> spin barrier safe
#define TPB  512
#define PTS  128          // points per block
#define SMEM_DYN (PTS * EE * 4)   // 32KB x stash

// Scratch ------------------------------------------------------------------
__device__ float    g_part[GRID * KK * EE];  // per-block centroid partial sums (2MB)
__device__ float    g_pcnt[GRID * KK];       // per-block cluster counts
__device__ float    g_cent[BB * KK * EE];    // normalized centroids
__device__ float    g_acc[3];                // L_v, L_d, L_r (unnormalized)
__device__ unsigned g_bar = 0;               // barrier/final counter (reset each run)

__device__ __forceinline__ void grid_barrier(unsigned target) {
    __syncthreads();
    if (threadIdx.x == 0) {
        __threadfence();
        atomicAdd(&g_bar, 1u);
        while (atomicAdd(&g_bar, 0u) < target) { __nanosleep(64); }
    }
    __syncthreads();
}

__global__ void __launch_bounds__(TPB) fused(const float* __restrict__ x,
                                             const float* __restrict__ m,
                                             float* __restrict__ out) {
    extern __shared__ float sx[];     // [PTS*EE] stashed x points
    __shared__ float sc[KK * EE];     // centroids for this block's batch
    __shared__ float ct[KK * EE];     // transposed centroids (phase 3)
    __shared__ int   slab[PTS];
    __shared__ int   ssorted[PTS];
    __shared__ int   sbin[KK], soff[KK], scur[KK];
    __shared__ float bsum, s_cntinv;

    int tid = threadIdx.x, lane = tid & 31, warp = tid >> 5;
    int blk = blockIdx.x;
    int pbase = blk * PTS;
    int b = blk >> 5;                 // 32 blocks per batch

    if (tid == 0) bsum = 0.0f;
    if (tid < KK) sbin[tid] = 0;
    if (blk == 0 && tid < 3) g_acc[tid] = 0.0f;
    __syncthreads();

    // ---- Phase 1a: coalesced x -> smem stash; labels via dot trick --------
    {
        const float4* x4 = (const float4*)(x + (size_t)pbase * EE);
        float4* sx4 = (float4*)sx;
        #pragma unroll
        for (int i = 0; i < 4; ++i)
            sx4[tid + i * TPB] = x4[tid + i * TPB];

        #pragma unroll
        for (int it = 0; it < 2; ++it) {
            int p  = it * 64 + warp * 4 + (lane >> 3);   // local point index
            int k0 = (lane & 7) * 4;
            float4 mv = *(const float4*)(m + (size_t)(pbase + p) * KK + k0);
            float s = mv.x * k0 + mv.y * (k0 + 1) + mv.z * (k0 + 2) + mv.w * (k0 + 3);
            s += __shfl_xor_sync(0xffffffffu, s, 1);
            s += __shfl_xor_sync(0xffffffffu, s, 2);
            s += __shfl_xor_sync(0xffffffffu, s, 4);
            if ((lane & 7) == 0) slab[p] = (int)(s + 0.5f);
        }
    }
    __syncthreads();

    // ---- Phase 1b: counting sort by label ---------------------------------
    if (tid < PTS) atomicAdd(&sbin[slab[tid]], 1);
    __syncthreads();
    if (tid < KK) {                   // warp 0 exclusive scan over 32 bins
        int c = sbin[tid];
        int pref = c;
        #pragma unroll
        for (int o = 1; o < 32; o <<= 1) {
            int nv = __shfl_up_sync(0xffffffffu, pref, o);
            if (lane >= o) pref += nv;
        }
        soff[tid] = pref - c;
        scur[tid] = pref - c;
    }
    __syncthreads();
    if (tid < PTS) {
        int pos = atomicAdd(&scur[slab[tid]], 1);
        ssorted[pos] = tid;
    }
    __syncthreads();

    // ---- Phase 1c: per-bin accumulation from smem (no atomics) ------------
    #pragma unroll
    for (int kb = 0; kb < 2; ++kb) {
        int k = warp * 2 + kb;
        int start = soff[k], cnt = sbin[k], end = start + cnt;
        float ax = 0.0f, ay = 0.0f;
        for (int base = start; base < end; base += 4) {
            float2 v0 = {0,0}, v1 = {0,0}, v2 = {0,0}, v3 = {0,0};
            v0 = *(const float2*)(sx + ssorted[base] * EE + lane * 2);
            if (base + 1 < end) v1 = *(const float2*)(sx + ssorted[base+1] * EE + lane * 2);
            if (base + 2 < end) v2 = *(const float2*)(sx + ssorted[base+2] * EE + lane * 2);
            if (base + 3 < end) v3 = *(const float2*)(sx + ssorted[base+3] * EE + lane * 2);
            ax += (v0.x + v1.x) + (v2.x + v3.x);
            ay += (v0.y + v1.y) + (v2.y + v3.y);
        }
        float2 acc = {ax, ay};
        *(float2*)(&g_part[(size_t)blk * (KK*EE) + k * EE + lane * 2]) = acc;
        if (lane == 0) g_pcnt[blk * KK + k] = (float)cnt;
    }

    grid_barrier(GRID);               // all partials visible

    // ---- Phase 2a: block i exclusively reduces (b,k)-row i -> g_cent ------
    {
        int rb = blk >> 5, rk = blk & 31;
        if (warp == 2) {              // one warp sums the 32 partial counts
            float c = __ldcg(&g_pcnt[((rb << 5) | lane) * KK + rk]);
            #pragma unroll
            for (int o = 16; o; o >>= 1) c += __shfl_xor_sync(0xffffffffu, c, o);
            if (lane == 0) s_cntinv = 1.0f / c;
        }
        __syncthreads();
        if (tid < EE) {
            float s0 = 0.0f, s1 = 0.0f, s2 = 0.0f, s3 = 0.0f;
            #pragma unroll
            for (int j = 0; j < 32; j += 4) {
                s0 += __ldcg(&g_part[(size_t)((rb << 5) | (j    )) * (KK*EE) + rk * EE + tid]);
                s1 += __ldcg(&g_part[(size_t)((rb << 5) | (j + 1)) * (KK*EE) + rk * EE + tid]);
                s2 += __ldcg(&g_part[(size_t)((rb << 5) | (j + 2)) * (KK*EE) + rk * EE + tid]);
                s3 += __ldcg(&g_part[(size_t)((rb << 5) | (j + 3)) * (KK*EE) + rk * EE + tid]);
            }
            g_cent[rb * (KK*EE) + rk * EE + tid] = ((s0 + s1) + (s2 + s3)) * s_cntinv;
        }
    }

    grid_barrier(2 * GRID);           // g_cent final

    // ---- Phase 2b: broadcast centroids, variance hinge from smem ----------
    ((float4*)sc)[tid] = __ldcg(((const float4*)(g_cent + b * (KK*EE))) + tid);
    __syncthreads();

    {
        int gid = tid >> 4, gl = tid & 15;      // 16-lane group per point
        float lv = 0.0f;
        #pragma unroll
        for (int it = 0; it < 2; ++it) {
            int iA = it * 64 + gid;
            int iB = iA + 32;
            int labA = slab[iA], labB = slab[iB];
            float4 xA = ((const float4*)sx)[iA * 16 + gl];
            float4 xB = ((const float4*)sx)[iB * 16 + gl];
            float4 cA = ((const float4*)sc)[labA * 16 + gl];
            float4 cB = ((const float4*)sc)[labB * 16 + gl];
            float a0 = xA.x - cA.x, a1 = xA.y - cA.y, a2 = xA.z - cA.z, a3 = xA.w - cA.w;
            float b0 = xB.x - cB.x, b1 = xB.y - cB.y, b2 = xB.z - cB.z, b3 = xB.w - cB.w;
            float sqA = a0 * a0 + a1 * a1 + a2 * a2 + a3 * a3;
            float sqB = b0 * b0 + b1 * b1 + b2 * b2 + b3 * b3;
            #pragma unroll
            for (int o = 8; o; o >>= 1) {
                sqA += __shfl_xor_sync(0xffffffffu, sqA, o);
                sqB += __shfl_xor_sync(0xffffffffu, sqB, o);
            }
            if (gl == 0) {
                float hA = sqrtf(sqA) - DELTA_V;
                float hB = sqrtf(sqB) - DELTA_V;
                if (hA > 0.0f) lv += hA * hA;
                if (hB > 0.0f) lv += hB * hB;
            }
        }
        if (gl == 0) atomicAdd(&bsum, lv);
        __syncthreads();
        if (tid == 0) atomicAdd(&g_acc[0], bsum);
    }

    // ---- Phase 3: pairwise hinge + reg term (one block per batch) ---------
    if ((blk & 31) == 0) {
        for (int i = tid; i < KK * EE; i += TPB) {
            int e = i >> 5, k = i & 31;
            ct[i] = sc[k * EE + e];           // ct[e][k], lane-contiguous
        }
        __syncthreads();

        float ld = 0.0f, lr = 0.0f;
        #pragma unroll
        for (int rep = 0; rep < 2; ++rep) {
            int pr = rep * TPB + tid;
            int k1 = pr >> 5, k2 = pr & 31;
            float sq = 0.0f;
            if (k1 == k2) {
                #pragma unroll
                for (int e = 0; e < EE; e++) { float v = sc[k1 * EE + e]; sq += v * v; }
                lr += sqrtf(sq);
            } else {
                #pragma unroll
                for (int e = 0; e < EE; e++) {
                    float d = sc[k1 * EE + e] - ct[e * KK + k2];
                    sq += d * d;
                }
                float h = 2.0f * DELTA_D - sqrtf(sq);
                if (h > 0.0f) ld += h * h;
            }
        }
        #pragma unroll
        for (int o = 16; o; o >>= 1) {
            ld += __shfl_xor_sync(0xffffffffu, ld, o);
            lr += __shfl_xor_sync(0xffffffffu, lr, o);
        }
        if (lane == 0) {
            atomicAdd(&g_acc[1], ld);
            atomicAdd(&g_acc[2], lr);
        }
    }

    // ---- Finalize ----------------------------------------------------------
    __syncthreads();
    if (tid == 0) {
        __threadfence();
        unsigned r = atomicAdd(&g_bar, 1u);
        if (r == 3 * GRID - 1) {
            float Lv = atomicAdd(&g_acc[0], 0.0f) / (float)(BB * NN);
            float Ld = atomicAdd(&g_acc[1], 0.0f) / (float)(BB * KK * (KK - 1));
            float Lr = atomicAdd(&g_acc[2], 0.0f) / (float)(BB * KK);
            out[0] = Lv + Ld + GAMMA * Lr;
            __threadfence();
            atomicExch(&g_bar, 0u);       // ready for next graph replay
        }
    }
}

// --------------------------------------------------------------------------
extern "C" void kernel_launch(void* const* d_in, const int* in_sizes, int n_in,
                              void* d_out, int out_size) {
    const float* x = (const float*)d_in[0];
    const float* m = (const float*)d_in[1];
    if (in_sizes[0] == BB * NN * KK && in_sizes[1] == BB * NN * EE) {
        x = (const float*)d_in[1];
        m = (const float*)d_in[0];
    }
    cudaFuncSetAttribute(fused, cudaFuncAttributeMaxDynamicSharedMemorySize, SMEM_DYN);
    fused<<<GRID, TPB, SMEM_DYN>>>(x, m, (float*)d_out);
}

// round 7
// speedup vs baseline: 2.0233x; 1.0499x over previous
#include <cuda_runtime.h>
#include <cuda_bf16.h>

// Fixed problem shape
#define BB 8
#define NN 4096
#define EE 64
#define KK 32

#define DELTA_V 0.5f
#define DELTA_D 1.5f
#define GAMMA   0.001f

#define GRID 256          // 2 blocks/SM, all co-resident -> spin barrier safe
#define TPB  512
#define PTS  128          // points per block
#define SMEM_DYN (PTS * EE * 4)   // 32KB x stash

// Scratch ------------------------------------------------------------------
__device__ float    g_part[GRID * KK * EE];  // per-block centroid partial sums (2MB)
__device__ float    g_pcnt[GRID * KK];       // per-block cluster counts
__device__ float    g_cent[BB * KK * EE];    // normalized centroids
__device__ float    g_acc[3];                // L_v, L_d, L_r (unnormalized)
__device__ unsigned g_bar = 0;               // barrier/final counter (reset each run)

__device__ __forceinline__ void grid_barrier(unsigned target) {
    __syncthreads();
    if (threadIdx.x == 0) {
        __threadfence();
        atomicAdd(&g_bar, 1u);                       // single RMW to arrive
        while (*(volatile unsigned*)&g_bar < target) // poll = plain load, no RMW
            __nanosleep(128);
    }
    __syncthreads();
}

__global__ void __launch_bounds__(TPB) fused(const float* __restrict__ x,
                                             const float* __restrict__ m,
                                             float* __restrict__ out) {
    extern __shared__ float sx[];     // [PTS*EE] stashed x points
    __shared__ float sc[KK * EE];     // centroids for this block's batch
    __shared__ float ct[KK * EE];     // phase-2a scratch, then transposed centroids
    __shared__ int   slab[PTS];
    __shared__ int   ssorted[PTS];
    __shared__ int   sbin[KK], soff[KK], scur[KK];
    __shared__ float bsum, s_cntinv;

    int tid = threadIdx.x, lane = tid & 31, warp = tid >> 5;
    int blk = blockIdx.x;
    int pbase = blk * PTS;
    int b = blk >> 5;                 // 32 blocks per batch

    if (tid == 0) bsum = 0.0f;
    if (tid < KK) sbin[tid] = 0;
    if (blk == 0 && tid < 3) g_acc[tid] = 0.0f;
    __syncthreads();

    // ---- Phase 1a: coalesced x -> smem stash; labels via dot trick --------
    {
        const float4* x4 = (const float4*)(x + (size_t)pbase * EE);
        float4* sx4 = (float4*)sx;
        #pragma unroll
        for (int i = 0; i < 4; ++i)
            sx4[tid + i * TPB] = x4[tid + i * TPB];

        #pragma unroll
        for (int it = 0; it < 2; ++it) {
            int p  = it * 64 + warp * 4 + (lane >> 3);   // local point index
            int k0 = (lane & 7) * 4;
            float4 mv = *(const float4*)(m + (size_t)(pbase + p) * KK + k0);
            float s = mv.x * k0 + mv.y * (k0 + 1) + mv.z * (k0 + 2) + mv.w * (k0 + 3);
            s += __shfl_xor_sync(0xffffffffu, s, 1);
            s += __shfl_xor_sync(0xffffffffu, s, 2);
            s += __shfl_xor_sync(0xffffffffu, s, 4);
            if ((lane & 7) == 0) slab[p] = (int)(s + 0.5f);
        }
    }
    __syncthreads();

    // ---- Phase 1b: counting sort by label ---------------------------------
    if (tid < PTS) atomicAdd(&sbin[slab[tid]], 1);
    __syncthreads();
    if (tid < KK) {                   // warp 0 exclusive scan over 32 bins
        int c = sbin[tid];
        int pref = c;
        #pragma unroll
        for (int o = 1; o < 32; o <<= 1) {
            int nv = __shfl_up_sync(0xffffffffu, pref, o);
            if (lane >= o) pref += nv;
        }
        soff[tid] = pref - c;
        scur[tid] = pref - c;
    }
    __syncthreads();
    if (tid < PTS) {
        int pos = atomicAdd(&scur[slab[tid]], 1);
        ssorted[pos] = tid;
    }
    __syncthreads();

    // ---- Phase 1c: per-bin accumulation from smem (no atomics) ------------
    #pragma unroll
    for (int kb = 0; kb < 2; ++kb) {
        int k = warp * 2 + kb;
        int start = soff[k], cnt = sbin[k], end = start + cnt;
        float ax = 0.0f, ay = 0.0f;
        for (int base = start; base < end; base += 4) {
            float2 v0 = {0,0}, v1 = {0,0}, v2 = {0,0}, v3 = {0,0};
            v0 = *(const float2*)(sx + ssorted[base] * EE + lane * 2);
            if (base + 1 < end) v1 = *(const float2*)(sx + ssorted[base+1] * EE + lane * 2);
            if (base + 2 < end) v2 = *(const float2*)(sx + ssorted[base+2] * EE + lane * 2);
            if (base + 3 < end) v3 = *(const float2*)(sx + ssorted[base+3] * EE + lane * 2);
            ax += (v0.x + v1.x) + (v2.x + v3.x);
            ay += (v0.y + v1.y) + (v2.y + v3.y);
        }
        float2 acc = {ax, ay};
        *(float2*)(&g_part[(size_t)blk * (KK*EE) + k * EE + lane * 2]) = acc;
        if (lane == 0) g_pcnt[blk * KK + k] = (float)cnt;
    }

    grid_barrier(GRID);               // all partials visible

    // ---- Phase 2a: block i exclusively reduces (b,k)-row i -> g_cent ------
    // 8 groups x 64 threads, 4 slices per group, then 64-thread tree.
    {
        int rb = blk >> 5, rk = blk & 31;
        if (warp == 0) {              // sum the 32 partial counts
            float c = __ldcg(&g_pcnt[((rb << 5) | lane) * KK + rk]);
            #pragma unroll
            for (int o = 16; o; o >>= 1) c += __shfl_xor_sync(0xffffffffu, c, o);
            if (lane == 0) s_cntinv = 1.0f / c;
        }
        int e = tid & 63, grp = tid >> 6;     // 8 groups of 64
        float s = 0.0f;
        #pragma unroll
        for (int j = 0; j < 4; ++j)
            s += __ldcg(&g_part[(size_t)((rb << 5) | (grp * 4 + j)) * (KK*EE) + rk * EE + e]);
        ct[grp * 64 + e] = s;                 // ct reused as scratch (512 floats)
        __syncthreads();
        if (tid < EE) {
            float t0 = ct[tid]       + ct[64 + tid];
            float t1 = ct[128 + tid] + ct[192 + tid];
            float t2 = ct[256 + tid] + ct[320 + tid];
            float t3 = ct[384 + tid] + ct[448 + tid];
            g_cent[rb * (KK*EE) + rk * EE + tid] = ((t0 + t1) + (t2 + t3)) * s_cntinv;
        }
    }

    grid_barrier(2 * GRID);           // g_cent final

    // ---- Phase 2b: broadcast centroids, variance hinge from smem ----------
    ((float4*)sc)[tid] = __ldcg(((const float4*)(g_cent + b * (KK*EE))) + tid);
    __syncthreads();

    {
        int gid = tid >> 4, gl = tid & 15;      // 16-lane group per point
        float lv = 0.0f;
        #pragma unroll
        for (int it = 0; it < 2; ++it) {
            int iA = it * 64 + gid;
            int iB = iA + 32;
            int labA = slab[iA], labB = slab[iB];
            float4 xA = ((const float4*)sx)[iA * 16 + gl];
            float4 xB = ((const float4*)sx)[iB * 16 + gl];
            float4 cA = ((const float4*)sc)[labA * 16 + gl];
            float4 cB = ((const float4*)sc)[labB * 16 + gl];
            float a0 = xA.x - cA.x, a1 = xA.y - cA.y, a2 = xA.z - cA.z, a3 = xA.w - cA.w;
            float b0 = xB.x - cB.x, b1 = xB.y - cB.y, b2 = xB.z - cB.z, b3 = xB.w - cB.w;
            float sqA = a0 * a0 + a1 * a1 + a2 * a2 + a3 * a3;
            float sqB = b0 * b0 + b1 * b1 + b2 * b2 + b3 * b3;
            #pragma unroll
            for (int o = 8; o; o >>= 1) {
                sqA += __shfl_xor_sync(0xffffffffu, sqA, o);
                sqB += __shfl_xor_sync(0xffffffffu, sqB, o);
            }
            if (gl == 0) {
                float hA = sqrtf(sqA) - DELTA_V;
                float hB = sqrtf(sqB) - DELTA_V;
                if (hA > 0.0f) lv += hA * hA;
                if (hB > 0.0f) lv += hB * hB;
            }
        }
        if (gl == 0) atomicAdd(&bsum, lv);
        __syncthreads();
        if (tid == 0) atomicAdd(&g_acc[0], bsum);
    }

    // ---- Phase 3: pairwise hinge + reg term (one block per batch) ---------
    if ((blk & 31) == 0) {
        __syncthreads();                      // ct scratch free again
        for (int i = tid; i < KK * EE; i += TPB) {
            int e = i >> 5, k = i & 31;
            ct[i] = sc[k * EE + e];           // ct[e][k], lane-contiguous
        }
        __syncthreads();

        float ld = 0.0f, lr = 0.0f;
        #pragma unroll
        for (int rep = 0; rep < 2; ++rep) {
            int pr = rep * TPB + tid;
            int k1 = pr >> 5, k2 = pr & 31;
            float sq = 0.0f;
            if (k1 == k2) {
                #pragma unroll
                for (int e = 0; e < EE; e++) { float v = sc[k1 * EE + e]; sq += v * v; }
                lr += sqrtf(sq);
            } else {
                #pragma unroll
                for (int e = 0; e < EE; e++) {
                    float d = sc[k1 * EE + e] - ct[e * KK + k2];
                    sq += d * d;
                }
                float h = 2.0f * DELTA_D - sqrtf(sq);
                if (h > 0.0f) ld += h * h;
            }
        }
        #pragma unroll
        for (int o = 16; o; o >>= 1) {
            ld += __shfl_xor_sync(0xffffffffu, ld, o);
            lr += __shfl_xor_sync(0xffffffffu, lr, o);
        }
        if (lane == 0) {
            atomicAdd(&g_acc[1], ld);
            atomicAdd(&g_acc[2], lr);
        }
    }

    // ---- Finalize ----------------------------------------------------------
    __syncthreads();
    if (tid == 0) {
        __threadfence();
        unsigned r = atomicAdd(&g_bar, 1u);
        if (r == 3 * GRID - 1) {
            float Lv = *(volatile float*)&g_acc[0] / (float)(BB * NN);
            float Ld = *(volatile float*)&g_acc[1] / (float)(BB * KK * (KK - 1));
            float Lr = *(volatile float*)&g_acc[2] / (float)(BB * KK);
            out[0] = Lv + Ld + GAMMA * Lr;
            __threadfence();
            atomicExch(&g_bar, 0u);       // ready for next graph replay
        }
    }
}

// --------------------------------------------------------------------------
extern "C" void kernel_launch(void* const* d_in, const int* in_sizes, int n_in,
                              void* d_out, int out_size) {
    const float* x = (const float*)d_in[0];
    const float* m = (const float*)d_in[1];
    if (in_sizes[0] == BB * NN * KK && in_sizes[1] == BB * NN * EE) {
        x = (const float*)d_in[1];
        m = (const float*)d_in[0];
    }
    cudaFuncSetAttribute(fused, cudaFuncAttributeMaxDynamicSharedMemorySize, SMEM_DYN);
    fused<<<GRID, TPB, SMEM_DYN>>>(x, m, (float*)d_out);
}

// round 8
// speedup vs baseline: 2.1002x; 1.0380x over previous
#include <cuda_runtime.h>
#include <cuda_bf16.h>

// Fixed problem shape
#define BB 8
#define NN 4096
#define EE 64
#define KK 32

#define DELTA_V 0.5f
#define DELTA_D 1.5f
#define GAMMA   0.001f

#define G1 256            // K1/K3 blocks
#define TPB 512
#define PTS 128           // points per K1/K3 block

// Scratch ------------------------------------------------------------------
__device__ float    g_part[G1 * KK * EE];   // per-block centroid partial sums (2MB)
__device__ float    g_pcnt[G1 * KK];        // per-block cluster counts
__device__ float    g_cent[BB * KK * EE];   // normalized centroids
__device__ int      g_lab[BB * NN];         // labels
__device__ float    g_acc[3];               // L_v, L_d, L_r (unnormalized)
__device__ unsigned g_bar = 0;              // K3 finalize counter (reset each run)

// ===========================================================================
// K1: labels + counting sort + per-bin partial sums
// ===========================================================================
__global__ void __launch_bounds__(TPB) k_partial(const float* __restrict__ x,
                                                 const float* __restrict__ m) {
    __shared__ int slab[PTS];
    __shared__ int ssorted[PTS];
    __shared__ int sbin[KK], soff[KK], scur[KK];

    int tid = threadIdx.x, lane = tid & 31, warp = tid >> 5;
    int blk = blockIdx.x;
    int pbase = blk * PTS;

    if (tid < KK) sbin[tid] = 0;
    if (blk == 0 && tid < 3) g_acc[tid] = 0.0f;
    __syncthreads();

    // labels via one-hot dot trick: label = sum_k k*m[k]
    #pragma unroll
    for (int it = 0; it < 2; ++it) {
        int p  = it * 64 + warp * 4 + (lane >> 3);
        int k0 = (lane & 7) * 4;
        float4 mv = *(const float4*)(m + (size_t)(pbase + p) * KK + k0);
        float s = mv.x * k0 + mv.y * (k0 + 1) + mv.z * (k0 + 2) + mv.w * (k0 + 3);
        s += __shfl_xor_sync(0xffffffffu, s, 1);
        s += __shfl_xor_sync(0xffffffffu, s, 2);
        s += __shfl_xor_sync(0xffffffffu, s, 4);
        if ((lane & 7) == 0) slab[p] = (int)(s + 0.5f);
    }
    __syncthreads();

    // counting sort
    if (tid < PTS) atomicAdd(&sbin[slab[tid]], 1);
    __syncthreads();
    if (tid < KK) {
        int c = sbin[tid];
        int pref = c;
        #pragma unroll
        for (int o = 1; o < 32; o <<= 1) {
            int nv = __shfl_up_sync(0xffffffffu, pref, o);
            if (lane >= o) pref += nv;
        }
        soff[tid] = pref - c;
        scur[tid] = pref - c;
    }
    __syncthreads();
    if (tid < PTS) {
        int pos = atomicAdd(&scur[slab[tid]], 1);
        ssorted[pos] = tid;
        g_lab[pbase + tid] = slab[tid];       // persist labels for K3
    }
    __syncthreads();

    // per-bin accumulation: gather x rows directly (coalesced 256B per point)
    #pragma unroll
    for (int kb = 0; kb < 2; ++kb) {
        int k = warp * 2 + kb;
        int start = soff[k], cnt = sbin[k], end = start + cnt;
        float ax = 0.0f, ay = 0.0f;
        for (int base = start; base < end; base += 4) {
            float2 v0 = {0,0}, v1 = {0,0}, v2 = {0,0}, v3 = {0,0};
            v0 = *(const float2*)(x + (size_t)(pbase + ssorted[base]) * EE + lane * 2);
            if (base + 1 < end) v1 = *(const float2*)(x + (size_t)(pbase + ssorted[base+1]) * EE + lane * 2);
            if (base + 2 < end) v2 = *(const float2*)(x + (size_t)(pbase + ssorted[base+2]) * EE + lane * 2);
            if (base + 3 < end) v3 = *(const float2*)(x + (size_t)(pbase + ssorted[base+3]) * EE + lane * 2);
            ax += (v0.x + v1.x) + (v2.x + v3.x);
            ay += (v0.y + v1.y) + (v2.y + v3.y);
        }
        float2 acc = {ax, ay};
        *(float2*)(&g_part[(size_t)blk * (KK*EE) + k * EE + lane * 2]) = acc;
        if (lane == 0) g_pcnt[blk * KK + k] = (float)cnt;
    }
}

// ===========================================================================
// K2: block i reduces (b,k)-row i -> normalized g_cent. 256 blocks x 256 thr.
// ===========================================================================
__global__ void __launch_bounds__(256) k_reduce() {
    __shared__ float part[256];
    __shared__ float s_cntinv;
    int tid = threadIdx.x, lane = tid & 31;
    int rb = blockIdx.x >> 5, rk = blockIdx.x & 31;

    if (tid < 32) {                     // sum 32 partial counts
        float c = __ldcg(&g_pcnt[((rb << 5) | lane) * KK + rk]);
        #pragma unroll
        for (int o = 16; o; o >>= 1) c += __shfl_xor_sync(0xffffffffu, c, o);
        if (lane == 0) s_cntinv = 1.0f / c;
    }

    int e = tid & 63, q = tid >> 6;     // 4 groups of 64, 8 slices each
    float s = 0.0f;
    #pragma unroll
    for (int j = 0; j < 8; ++j)
        s += __ldcg(&g_part[(size_t)((rb << 5) | (q * 8 + j)) * (KK*EE) + rk * EE + e]);
    part[q * 64 + e] = s;
    __syncthreads();
    if (tid < EE) {
        float t = ((part[tid] + part[64 + tid]) + (part[128 + tid] + part[192 + tid]));
        g_cent[rb * (KK*EE) + rk * EE + tid] = t * s_cntinv;
    }
}

// ===========================================================================
// K3: variance hinge (all blocks) + pairs/reg (8 blocks) + finalize
// ===========================================================================
__global__ void __launch_bounds__(TPB) k_loss(const float* __restrict__ x,
                                              float* __restrict__ out) {
    __shared__ float sc[KK * EE];
    __shared__ float ct[KK * EE];
    __shared__ int   slab[PTS];
    __shared__ float bsum;

    int tid = threadIdx.x, lane = tid & 31;
    int blk = blockIdx.x;
    int pbase = blk * PTS;
    int b = blk >> 5;

    if (tid == 0) bsum = 0.0f;
    ((float4*)sc)[tid] = __ldcg(((const float4*)(g_cent + b * (KK*EE))) + tid);
    if (tid < PTS) slab[tid] = g_lab[pbase + tid];
    __syncthreads();

    // variance hinge: 16-lane group per point, 2-pt ILP, x from warm L2
    {
        int gid = tid >> 4, gl = tid & 15;
        float lv = 0.0f;
        #pragma unroll
        for (int it = 0; it < 2; ++it) {
            int iA = it * 64 + gid;
            int iB = iA + 32;
            int labA = slab[iA], labB = slab[iB];
            float4 xA = *(const float4*)(x + (size_t)(pbase + iA) * EE + gl * 4);
            float4 xB = *(const float4*)(x + (size_t)(pbase + iB) * EE + gl * 4);
            float4 cA = ((const float4*)sc)[labA * 16 + gl];
            float4 cB = ((const float4*)sc)[labB * 16 + gl];
            float a0 = xA.x - cA.x, a1 = xA.y - cA.y, a2 = xA.z - cA.z, a3 = xA.w - cA.w;
            float b0 = xB.x - cB.x, b1 = xB.y - cB.y, b2 = xB.z - cB.z, b3 = xB.w - cB.w;
            float sqA = a0 * a0 + a1 * a1 + a2 * a2 + a3 * a3;
            float sqB = b0 * b0 + b1 * b1 + b2 * b2 + b3 * b3;
            #pragma unroll
            for (int o = 8; o; o >>= 1) {
                sqA += __shfl_xor_sync(0xffffffffu, sqA, o);
                sqB += __shfl_xor_sync(0xffffffffu, sqB, o);
            }
            if (gl == 0) {
                float hA = sqrtf(sqA) - DELTA_V;
                float hB = sqrtf(sqB) - DELTA_V;
                if (hA > 0.0f) lv += hA * hA;
                if (hB > 0.0f) lv += hB * hB;
            }
        }
        if (gl == 0) atomicAdd(&bsum, lv);
        __syncthreads();
        if (tid == 0) atomicAdd(&g_acc[0], bsum);
    }

    // pairwise hinge + reg term (one block per batch)
    if ((blk & 31) == 0) {
        for (int i = tid; i < KK * EE; i += TPB) {
            int e = i >> 5, k = i & 31;
            ct[i] = sc[k * EE + e];            // transposed, lane-contiguous
        }
        __syncthreads();

        float ld = 0.0f, lr = 0.0f;
        #pragma unroll
        for (int rep = 0; rep < 2; ++rep) {
            int pr = rep * TPB + tid;
            int k1 = pr >> 5, k2 = pr & 31;
            float sq = 0.0f;
            if (k1 == k2) {
                #pragma unroll
                for (int e = 0; e < EE; e++) { float v = sc[k1 * EE + e]; sq += v * v; }
                lr += sqrtf(sq);
            } else {
                #pragma unroll
                for (int e = 0; e < EE; e++) {
                    float d = sc[k1 * EE + e] - ct[e * KK + k2];
                    sq += d * d;
                }
                float h = 2.0f * DELTA_D - sqrtf(sq);
                if (h > 0.0f) ld += h * h;
            }
        }
        #pragma unroll
        for (int o = 16; o; o >>= 1) {
            ld += __shfl_xor_sync(0xffffffffu, ld, o);
            lr += __shfl_xor_sync(0xffffffffu, lr, o);
        }
        if (lane == 0) {
            atomicAdd(&g_acc[1], ld);
            atomicAdd(&g_acc[2], lr);
        }
    }

    // finalize: last arrival writes output (no spinning)
    __syncthreads();
    if (tid == 0) {
        __threadfence();
        unsigned r = atomicAdd(&g_bar, 1u);
        if (r == G1 - 1) {
            float Lv = *(volatile float*)&g_acc[0] / (float)(BB * NN);
            float Ld = *(volatile float*)&g_acc[1] / (float)(BB * KK * (KK - 1));
            float Lr = *(volatile float*)&g_acc[2] / (float)(BB * KK);
            out[0] = Lv + Ld + GAMMA * Lr;
            __threadfence();
            atomicExch(&g_bar, 0u);            // ready for next replay
        }
    }
}

// --------------------------------------------------------------------------
extern "C" void kernel_launch(void* const* d_in, const int* in_sizes, int n_in,
                              void* d_out, int out_size) {
    const float* x = (const float*)d_in[0];
    const float* m = (const float*)d_in[1];
    if (in_sizes[0] == BB * NN * KK && in_sizes[1] == BB * NN * EE) {
        x = (const float*)d_in[1];
        m = (const float*)d_in[0];
    }
    k_partial<<<G1, TPB>>>(x, m);
    k_reduce<<<G1, 256>>>();
    k_loss<<<G1, TPB>>>(x, (float*)d_out);
}